// round 1
// baseline (speedup 1.0000x reference)
#include <cuda_runtime.h>
#include <math.h>
#include <stdint.h>

// Problem constants (fixed shapes for this problem)
#define NN 10000
#define EE 160000
#define CC 128
#define EPW 4

// ---------------- scratch (device globals; no allocation allowed) -------------
__device__ float4 g_h4  [NN*CC/4];        // h = node_feats @ W_up            [N,128]
__device__ float4 g_z4  [EE*64/4];        // radial hidden                    [E,64]
__device__ float4 g_agg4[9*NN*CC/4];      // scattered messages, comp-major   [9][N][128]
__device__ float4 g_svt4[9*NN*CC/4];      // s,v(3),t(5)                      [9][N][128]
__device__ float4 g_B4  [4*NN*CC/4];      // B0, B1x,B1y,B1z                  [4][N][128]
__device__ float4 g_h04 [NN*CC/4];        // h0                               [N,128]
__device__ float4 g_h14 [3*NN*CC/4];      // h1 comp-major                    [3][N][128]
__device__ float4 g_zr4 [NN*64/4];        // readout hidden                   [N,64]

// ---------------- small helpers ----------------
__device__ __forceinline__ void red4(float* p, float a, float b, float c, float d) {
    asm volatile("red.global.add.v4.f32 [%0], {%1,%2,%3,%4};"
                 :: "l"(p), "f"(a), "f"(b), "f"(c), "f"(d) : "memory");
}

__global__ void zero_agg_k(int n4) {
    int i = blockIdx.x * blockDim.x + threadIdx.x;
    if (i < n4) g_agg4[i] = make_float4(0.f, 0.f, 0.f, 0.f);
}

// ---------------- generic fp32 GEMM: C = act(A@B + bias + ecol*erow) ----------
// 64x64 tile, BK=16, 256 threads, 4x4 per thread. Requires K % 16 == 0.
template<int ACT>
__global__ void __launch_bounds__(256)
gemm_k(const float* __restrict__ A, const float* __restrict__ B,
       float* __restrict__ C, int M, int N, int K,
       const float* __restrict__ bias,
       const float* __restrict__ ecol, const float* __restrict__ erow)
{
    __shared__ float As[16][68];
    __shared__ float Bs[16][64];
    int tid = threadIdx.x;
    int tx = tid & 15, ty = tid >> 4;
    int bm = blockIdx.y * 64, bn = blockIdx.x * 64;

    float acc[4][4];
#pragma unroll
    for (int i = 0; i < 4; i++)
#pragma unroll
        for (int j = 0; j < 4; j++) acc[i][j] = 0.f;

    int mi = tid >> 2;   // 0..63
    int kq = tid & 3;    // which float4 of the 16-wide K slab
    bool mvalid = (bm + mi) < M;
    const float* Arow = A + (size_t)(bm + mi) * K;

    for (int k0 = 0; k0 < K; k0 += 16) {
        float4 av = make_float4(0.f, 0.f, 0.f, 0.f);
        if (mvalid) av = *(const float4*)(Arow + k0 + kq * 4);
        As[kq*4+0][mi] = av.x;
        As[kq*4+1][mi] = av.y;
        As[kq*4+2][mi] = av.z;
        As[kq*4+3][mi] = av.w;
#pragma unroll
        for (int l = 0; l < 4; l++) {
            int idx = tid + l * 256;
            int ki = idx >> 6, ni = idx & 63;
            int n = bn + ni;
            Bs[ki][ni] = (n < N) ? B[(size_t)(k0 + ki) * N + n] : 0.f;
        }
        __syncthreads();
#pragma unroll
        for (int kk = 0; kk < 16; kk++) {
            float4 a4 = *(const float4*)(&As[kk][ty * 4]);
            float4 b4 = *(const float4*)(&Bs[kk][tx * 4]);
            float a[4] = {a4.x, a4.y, a4.z, a4.w};
            float b[4] = {b4.x, b4.y, b4.z, b4.w};
#pragma unroll
            for (int i = 0; i < 4; i++)
#pragma unroll
                for (int j = 0; j < 4; j++)
                    acc[i][j] = fmaf(a[i], b[j], acc[i][j]);
        }
        __syncthreads();
    }
#pragma unroll
    for (int i = 0; i < 4; i++) {
        int m = bm + ty * 4 + i;
        if (m >= M) continue;
        float ec = ecol ? ecol[m] : 0.f;
#pragma unroll
        for (int j = 0; j < 4; j++) {
            int n = bn + tx * 4 + j;
            if (n >= N) continue;
            float v = acc[i][j];
            if (bias) v += bias[n];
            if (ecol) v = fmaf(ec, erow[n], v);
            if (ACT)  v = v / (1.f + __expf(-v));
            C[(size_t)m * N + n] = v;
        }
    }
}

// ---------------- edge kernel: R = z@Wr2 (smem), messages, scatter -----------
__global__ void __launch_bounds__(256)
edge_kernel(const float* __restrict__ vectors,
            const int*   __restrict__ edge_index,
            const float* __restrict__ Wr2,
            int E, int N)
{
    extern __shared__ float sm[];
    float* wsm = sm;  // Wr2: 64*384 floats
    int lane = threadIdx.x & 31, wid = threadIdx.x >> 5;
    float* zsh = sm + 64 * 384 + wid * (EPW * 64);

    for (int i = threadIdx.x; i < 64 * 384; i += blockDim.x) wsm[i] = Wr2[i];
    __syncthreads();

    const float4* w4  = (const float4*)wsm;   // 96 float4 per k-row
    const float*  zg  = (const float*)g_z4;
    const float4* h4  = (const float4*)g_h4;
    float*        agg = (float*)g_agg4;
    int NC = N * CC;

    int gw = blockIdx.x * (blockDim.x >> 5) + wid;
    int nw = gridDim.x * (blockDim.x >> 5);
    int ngroups = (E + EPW - 1) / EPW;

    for (int g = gw; g < ngroups; g += nw) {
        int e0 = g * EPW;
        int cnt = E - e0; if (cnt > EPW) cnt = EPW;
        for (int j = 0; j < cnt; j++) {
            zsh[j * 64 + lane]      = zg[(size_t)(e0 + j) * 64 + lane];
            zsh[j * 64 + lane + 32] = zg[(size_t)(e0 + j) * 64 + lane + 32];
        }
        __syncwarp();

        float4 acc[EPW][3];
#pragma unroll
        for (int j = 0; j < EPW; j++)
#pragma unroll
            for (int p = 0; p < 3; p++) acc[j][p] = make_float4(0.f, 0.f, 0.f, 0.f);

#pragma unroll 4
        for (int k = 0; k < 64; k++) {
            float4 b0 = w4[k * 96 +      lane];
            float4 b1 = w4[k * 96 + 32 + lane];
            float4 b2 = w4[k * 96 + 64 + lane];
#pragma unroll
            for (int j = 0; j < EPW; j++) {
                float zk = zsh[j * 64 + k];
                acc[j][0].x = fmaf(zk, b0.x, acc[j][0].x);
                acc[j][0].y = fmaf(zk, b0.y, acc[j][0].y);
                acc[j][0].z = fmaf(zk, b0.z, acc[j][0].z);
                acc[j][0].w = fmaf(zk, b0.w, acc[j][0].w);
                acc[j][1].x = fmaf(zk, b1.x, acc[j][1].x);
                acc[j][1].y = fmaf(zk, b1.y, acc[j][1].y);
                acc[j][1].z = fmaf(zk, b1.z, acc[j][1].z);
                acc[j][1].w = fmaf(zk, b1.w, acc[j][1].w);
                acc[j][2].x = fmaf(zk, b2.x, acc[j][2].x);
                acc[j][2].y = fmaf(zk, b2.y, acc[j][2].y);
                acc[j][2].z = fmaf(zk, b2.z, acc[j][2].z);
                acc[j][2].w = fmaf(zk, b2.w, acc[j][2].w);
            }
        }

        for (int j = 0; j < cnt; j++) {
            int e = e0 + j;
            int snd = edge_index[e];
            int rcv = edge_index[E + e];
            float4 hs = h4[(size_t)snd * 32 + lane];

            float vx = vectors[3 * e], vy = vectors[3 * e + 1], vz = vectors[3 * e + 2];
            float nrm = sqrtf(fmaf(vx, vx, fmaf(vy, vy, vz * vz)));
            float inv = 1.f / (nrm + 1e-9f);
            float ux = vx * inv, uy = vy * inv, uz = vz * inv;
            const float s3   = 1.7320508075688772f;
            const float s15  = 3.8729833462074170f;
            const float s15h = 1.9364916731037085f;
            const float s5h  = 1.1180339887498949f;
            float Y1x = s3 * ux, Y1y = s3 * uy, Y1z = s3 * uz;
            float Y2a = s15 * ux * uy;
            float Y2b = s15 * uy * uz;
            float Y2c = s5h * (3.f * uz * uz - 1.f);
            float Y2d = s15 * ux * uz;
            float Y2e = s15h * (ux * ux - uy * uy);

            const float ia = 0.0625f;  // fold 1/AVG into coefficients
            float c0x = hs.x * acc[j][0].x * ia, c0y = hs.y * acc[j][0].y * ia,
                  c0z = hs.z * acc[j][0].z * ia, c0w = hs.w * acc[j][0].w * ia;
            float c1x = hs.x * acc[j][1].x * ia, c1y = hs.y * acc[j][1].y * ia,
                  c1z = hs.z * acc[j][1].z * ia, c1w = hs.w * acc[j][1].w * ia;
            float c2x = hs.x * acc[j][2].x * ia, c2y = hs.y * acc[j][2].y * ia,
                  c2z = hs.z * acc[j][2].z * ia, c2w = hs.w * acc[j][2].w * ia;

            float* base = agg + (size_t)rcv * CC + lane * 4;
            red4(base,            c0x,       c0y,       c0z,       c0w);
            red4(base + 1 * NC,   c1x * Y1x, c1y * Y1x, c1z * Y1x, c1w * Y1x);
            red4(base + 2 * NC,   c1x * Y1y, c1y * Y1y, c1z * Y1y, c1w * Y1y);
            red4(base + 3 * NC,   c1x * Y1z, c1y * Y1z, c1z * Y1z, c1w * Y1z);
            red4(base + 4 * NC,   c2x * Y2a, c2y * Y2a, c2z * Y2a, c2w * Y2a);
            red4(base + 5 * NC,   c2x * Y2b, c2y * Y2b, c2z * Y2b, c2w * Y2b);
            red4(base + 6 * NC,   c2x * Y2c, c2y * Y2c, c2z * Y2c, c2w * Y2c);
            red4(base + 7 * NC,   c2x * Y2d, c2y * Y2d, c2z * Y2d, c2w * Y2d);
            red4(base + 8 * NC,   c2x * Y2e, c2y * Y2e, c2z * Y2e, c2w * Y2e);
        }
        __syncwarp();
    }
}

// ---------------- symmetric contraction (elementwise over n,c) ---------------
__global__ void contract_k(const float* __restrict__ w0, const float* __restrict__ w1, int N)
{
    int i = blockIdx.x * blockDim.x + threadIdx.x;
    int NC = N * CC;
    if (i >= NC) return;
    int c = i & (CC - 1);
    const float* svt = (const float*)g_svt4;
    float* Bv = (float*)g_B4;

    float s  = svt[i];
    float vx = svt[NC + i], vy = svt[2 * NC + i], vz = svt[3 * NC + i];
    float ta = svt[4 * NC + i], tb = svt[5 * NC + i], tcm = svt[6 * NC + i];
    float td = svt[7 * NC + i], te = svt[8 * NC + i];

    float c3 = tcm * 0.5773502691896258f;  // c / sqrt(3)
    float Txx = te - c3, Txy = ta, Txz = td;
    float Tyy = -te - c3, Tyz = tb;
    float Tzz = 2.f * c3;

    float v2 = vx * vx + vy * vy + vz * vz;
    float t2 = ta * ta + tb * tb + tcm * tcm + td * td + te * te;
    float Tvx = Txx * vx + Txy * vy + Txz * vz;
    float Tvy = Txy * vx + Tyy * vy + Tyz * vz;
    float Tvz = Txz * vx + Tyz * vy + Tzz * vz;
    float vTv = vx * Tvx + vy * Tvy + vz * Tvz;

    float B0 = w0[c] * s + w0[CC + c] * s * s + w0[2 * CC + c] * v2 + w0[3 * CC + c] * t2
             + w0[4 * CC + c] * s * s * s + w0[5 * CC + c] * s * v2
             + w0[6 * CC + c] * s * t2 + w0[7 * CC + c] * vTv;

    float k0 = w1[c], k1 = w1[CC + c], k2 = w1[2 * CC + c];
    float k3 = w1[3 * CC + c], k4 = w1[4 * CC + c], k5 = w1[5 * CC + c];
    float f = k0 + k1 * s + k3 * s * s + k4 * v2;   // coefficient on v
    float gT = k2 + k5 * s;                          // coefficient on Tv
    float B1x = f * vx + gT * Tvx;
    float B1y = f * vy + gT * Tvy;
    float B1z = f * vz + gT * Tvz;

    Bv[i] = B0;
    Bv[NC + i] = B1x;
    Bv[2 * NC + i] = B1y;
    Bv[3 * NC + i] = B1z;
}

// ---------------- finalize: gate, vec, node_feats_out ------------------------
__global__ void final_k(const float* __restrict__ W3, const float* __restrict__ wv,
                        float* __restrict__ out, int N)
{
    int lane = threadIdx.x & 31;
    int node = (blockIdx.x * blockDim.x + threadIdx.x) >> 5;
    if (node >= N) return;
    int NC = N * CC;
    const float* zr = (const float*)g_zr4;
    const float* h0 = (const float*)g_h04;
    const float* h1 = (const float*)g_h14;

    float gate = zr[node * 64 + lane] * W3[lane] + zr[node * 64 + 32 + lane] * W3[32 + lane];
    float sx = 0.f, sy = 0.f, sz = 0.f;
#pragma unroll
    for (int c = lane; c < CC; c += 32) {
        float w = wv[c];
        sx = fmaf(h1[node * CC + c], w, sx);
        sy = fmaf(h1[NC + node * CC + c], w, sy);
        sz = fmaf(h1[2 * NC + node * CC + c], w, sz);
    }
#pragma unroll
    for (int off = 16; off; off >>= 1) {
        gate += __shfl_xor_sync(0xffffffffu, gate, off);
        sx   += __shfl_xor_sync(0xffffffffu, sx, off);
        sy   += __shfl_xor_sync(0xffffffffu, sy, off);
        sz   += __shfl_xor_sync(0xffffffffu, sz, off);
    }
    if (lane == 0) {
        float* ov = out + (size_t)N * 128 + (size_t)node * 3;
        ov[0] = sx * gate;
        ov[1] = sy * gate;
        ov[2] = sz * gate;
    }
    float* nf = out + (size_t)N * 131 + (size_t)node * 512;
#pragma unroll
    for (int c = lane; c < CC; c += 32) {
        nf[c] = h0[node * CC + c];
        nf[128 + 3 * c + 0] = h1[node * CC + c];
        nf[128 + 3 * c + 1] = h1[NC + node * CC + c];
        nf[128 + 3 * c + 2] = h1[2 * NC + node * CC + c];
    }
}

// ---------------- host launcher ----------------------------------------------
extern "C" void kernel_launch(void* const* d_in, const int* in_sizes, int n_in,
                              void* d_out, int out_size)
{
    const float* vectors    = (const float*)d_in[0];
    const float* lengths    = (const float*)d_in[1];
    const float* node_feats = (const float*)d_in[2];
    const float* edge_feats = (const float*)d_in[3];
    const int*   edge_index = (const int*)  d_in[4];
    const float* W_up = (const float*)d_in[5];
    const float* Wr1  = (const float*)d_in[6];
    const float* br1  = (const float*)d_in[7];
    const float* Wr2  = (const float*)d_in[8];
    const float* Wl0  = (const float*)d_in[9];
    const float* Wl1  = (const float*)d_in[10];
    const float* Wl2  = (const float*)d_in[11];
    const float* w0   = (const float*)d_in[12];
    const float* w1   = (const float*)d_in[13];
    const float* P0   = (const float*)d_in[14];
    const float* P1   = (const float*)d_in[15];
    const float* W1   = (const float*)d_in[16];
    const float* b1   = (const float*)d_in[17];
    const float* W2   = (const float*)d_in[18];
    const float* W3   = (const float*)d_in[19];
    const float* wv   = (const float*)d_in[20];
    float* out = (float*)d_out;

    int E = in_sizes[1];           // lengths is [E,1]
    int N = in_sizes[2] / CC;      // node_feats is [N,128]
    int NC = N * CC;

    float *p_h, *p_z, *p_agg, *p_svt, *p_B, *p_h0, *p_h1, *p_zr;
    cudaGetSymbolAddress((void**)&p_h,   g_h4);
    cudaGetSymbolAddress((void**)&p_z,   g_z4);
    cudaGetSymbolAddress((void**)&p_agg, g_agg4);
    cudaGetSymbolAddress((void**)&p_svt, g_svt4);
    cudaGetSymbolAddress((void**)&p_B,   g_B4);
    cudaGetSymbolAddress((void**)&p_h0,  g_h04);
    cudaGetSymbolAddress((void**)&p_h1,  g_h14);
    cudaGetSymbolAddress((void**)&p_zr,  g_zr4);

    // 0) zero the scatter accumulators
    int n4 = 9 * NC / 4;
    zero_agg_k<<<(n4 + 255) / 256, 256>>>(n4);

    // 1) h = node_feats @ W_up   [N,128]
    gemm_k<0><<<dim3(2, (N + 63) / 64), 256>>>(node_feats, W_up, p_h, N, 128, 128,
                                               nullptr, nullptr, nullptr);

    // 2) z = silu(edge_feats @ Wr1[:128] + lengths * Wr1[128] + br1)   [E,64]
    gemm_k<1><<<dim3(1, (E + 63) / 64), 256>>>(edge_feats, Wr1, p_z, E, 64, 128,
                                               br1, lengths, Wr1 + 128 * 64);

    // 3) edge kernel: R = z@Wr2 (smem), messages, vector red into agg
    int smem_bytes = (64 * 384 + 8 * EPW * 64) * 4;
    cudaFuncSetAttribute(edge_kernel, cudaFuncAttributeMaxDynamicSharedMemorySize, smem_bytes);
    edge_kernel<<<296, 256, smem_bytes>>>(vectors, edge_index, Wr2, E, N);

    // 4) s,v,t: 9 GEMMs [N,128]@[128,128]
    dim3 gn(2, (N + 63) / 64);
    gemm_k<0><<<gn, 256>>>(p_agg, Wl0, p_svt, N, 128, 128, nullptr, nullptr, nullptr);
    for (int x = 0; x < 3; x++)
        gemm_k<0><<<gn, 256>>>(p_agg + (size_t)(1 + x) * NC, Wl1,
                               p_svt + (size_t)(1 + x) * NC, N, 128, 128,
                               nullptr, nullptr, nullptr);
    for (int x = 0; x < 5; x++)
        gemm_k<0><<<gn, 256>>>(p_agg + (size_t)(4 + x) * NC, Wl2,
                               p_svt + (size_t)(4 + x) * NC, N, 128, 128,
                               nullptr, nullptr, nullptr);

    // 5) symmetric contraction -> B0, B1
    contract_k<<<(NC + 255) / 256, 256>>>(w0, w1, N);

    // 6) h0 = B0@P0, h1x = B1x@P1
    gemm_k<0><<<gn, 256>>>(p_B, P0, p_h0, N, 128, 128, nullptr, nullptr, nullptr);
    for (int x = 0; x < 3; x++)
        gemm_k<0><<<gn, 256>>>(p_B + (size_t)(1 + x) * NC, P1,
                               p_h1 + (size_t)x * NC, N, 128, 128,
                               nullptr, nullptr, nullptr);

    // 7) zr = silu(h0@W1 + b1)
    gemm_k<1><<<dim3(1, (N + 63) / 64), 256>>>(p_h0, W1, p_zr, N, 64, 128,
                                               b1, nullptr, nullptr);

    // 8) scal = zr@W2  -> directly into d_out[0 : N*128]
    gemm_k<0><<<dim3(2, (N + 63) / 64), 256>>>(p_zr, W2, out, N, 128, 64,
                                               nullptr, nullptr, nullptr);

    // 9) gate, vec, node_feats_out
    final_k<<<(N * 32 + 255) / 256, 256>>>(W3, wv, out, N);
}